// round 15
// baseline (speedup 1.0000x reference)
#include <cuda_runtime.h>
#include <cuda_fp16.h>
#include <math.h>

// Problem constants (fixed by setup_inputs)
#define NTOK 8192      // B*S
#define HDIM 1024
#define IDIM 2048
#define EEXP 8
#define TOPK 2

// GEMM tiling
#define TM 128
#define TN 128
#define TK 32
#define AP 40          // padded k-row length (fp16): 80B stride, conflict-free LDSM

#define GU_SMEM (1024 + 3 * 2 * TM * AP * 2)   // prow/toks + Ah,Bg,Bu double-buffered
#define AUXB 64                                 // aux partial blocks

// ---------------- device scratch ----------------
__device__ int   g_cnt[EEXP];
__device__ int   g_pairs[EEXP * NTOK];
__device__ float g_tokw[NTOK * 2];
__device__ int   g_toke[NTOK * 2];
__device__ float g_selw[NTOK * 2];
__device__ float g_auxw[AUXB * EEXP];   // per-block per-expert selw sums
__device__ float g_auxc[AUXB * EEXP];   // per-block per-expert counts

// all GEMM operands single-rounded fp16
__device__ __half g_xh[NTOK * HDIM];
__device__ __half g_wg[EEXP * IDIM * HDIM];   // gate, transposed [e][i][h]
__device__ __half g_wu[EEXP * IDIM * HDIM];   // up, transposed [e][i][h]
__device__ __half g_wd[EEXP * HDIM * IDIM];   // down, transposed [e][h][i]
__device__ __half g_hb[NTOK * 2 * IDIM];      // silu(g)*u (fp16)  [pair][I]

// ---------------- helpers ----------------
__device__ __forceinline__ void mma_f16(float *d, const unsigned *a, const unsigned *b) {
    asm volatile("mma.sync.aligned.m16n8k16.row.col.f32.f16.f16.f32 "
        "{%0,%1,%2,%3}, {%4,%5,%6,%7}, {%8,%9}, {%0,%1,%2,%3};\n"
        : "+f"(d[0]), "+f"(d[1]), "+f"(d[2]), "+f"(d[3])
        : "r"(a[0]), "r"(a[1]), "r"(a[2]), "r"(a[3]), "r"(b[0]), "r"(b[1]));
}

__device__ __forceinline__ void ldsm4(unsigned &r0, unsigned &r1, unsigned &r2, unsigned &r3,
                                      unsigned a) {
    asm volatile("ldmatrix.sync.aligned.m8n8.x4.shared.b16 {%0,%1,%2,%3}, [%4];\n"
        : "=r"(r0), "=r"(r1), "=r"(r2), "=r"(r3) : "r"(a));
}

__device__ __forceinline__ void cpa16(void* smem, const void* g) {
    unsigned s = (unsigned)__cvta_generic_to_shared(smem);
    asm volatile("cp.async.cg.shared.global [%0], [%1], 16;\n" :: "r"(s), "l"(g));
}
__device__ __forceinline__ void cpa_commit() {
    asm volatile("cp.async.commit_group;\n");
}
__device__ __forceinline__ void cpa_wait0() {
    asm volatile("cp.async.wait_group 0;\n");
}

// ---------------- reset ----------------
__global__ void reset_kernel() {
    if (threadIdx.x < EEXP) g_cnt[threadIdx.x] = 0;
}

// ---------------- zero output (d_out is poisoned; atomics need 0 base) ----------------
__global__ void zero_y_kernel(float* __restrict__ y) {
    int idx = blockIdx.x * blockDim.x + threadIdx.x;
    float4 z; z.x = 0.f; z.y = 0.f; z.z = 0.f; z.w = 0.f;
    ((float4*)y)[idx] = z;
}

// ---------------- transpose weights to fp16: src [E][R][C] -> dst [E][C][R] ----------------
// 64x64 tiles; float4 loads; uint4 (8-half) vectorized transposed stores.
// W selects destinations IN DEVICE CODE (never pass __device__ globals from host:
// that passes the host shadow symbol; ATS silently dereferences host memory).
template<int W>
__global__ void transpose_half_kernel(const float* __restrict__ src, int R, int C) {
    __half* dh = (W == 0) ? g_wg : (W == 1) ? g_wu : g_wd;
    __shared__ float s[64][65];
    int e = blockIdx.z;
    int r0 = blockIdx.y * 64, c0 = blockIdx.x * 64;
    int tid = threadIdx.x;
    const float* sp = src + ((size_t)e * R + r0) * C + c0;
#pragma unroll
    for (int k = 0; k < 4; k++) {
        int u = tid + k * 256;
        int row = u >> 4;
        int cq = (u & 15) * 4;
        float4 v = *(const float4*)(sp + (size_t)row * C + cq);
        s[row][cq + 0] = v.x; s[row][cq + 1] = v.y;
        s[row][cq + 2] = v.z; s[row][cq + 3] = v.w;
    }
    __syncthreads();
    size_t dbase = ((size_t)e * C + c0) * R + r0;
#pragma unroll
    for (int k = 0; k < 2; k++) {
        int u = tid + k * 256;
        int c = u >> 3;
        int rc = (u & 7) * 8;
        __half2 p0 = __floats2half2_rn(s[rc + 0][c], s[rc + 1][c]);
        __half2 p1 = __floats2half2_rn(s[rc + 2][c], s[rc + 3][c]);
        __half2 p2 = __floats2half2_rn(s[rc + 4][c], s[rc + 5][c]);
        __half2 p3 = __floats2half2_rn(s[rc + 6][c], s[rc + 7][c]);
        uint4 o;
        o.x = *reinterpret_cast<unsigned*>(&p0);
        o.y = *reinterpret_cast<unsigned*>(&p1);
        o.z = *reinterpret_cast<unsigned*>(&p2);
        o.w = *reinterpret_cast<unsigned*>(&p3);
        *(uint4*)(dh + dbase + (size_t)c * R + rc) = o;
    }
}

// ---------------- router: one warp per token, float4 loads (also emits x as fp16) ----------------
__global__ void router_kernel(const float* __restrict__ x,
                              const float* __restrict__ gw) {
    int t = blockIdx.x * (blockDim.x >> 5) + (threadIdx.x >> 5);
    int lane = threadIdx.x & 31;
    if (t >= NTOK) return;
    const float* xr = x + (size_t)t * HDIM;
    __half* xo = g_xh + (size_t)t * HDIM;
    float acc[EEXP];
#pragma unroll
    for (int e = 0; e < EEXP; e++) acc[e] = 0.f;
#pragma unroll
    for (int k = 0; k < HDIM / 128; k++) {
        int h = k * 128 + lane * 4;
        float4 v = *(const float4*)(xr + h);
        __half2 p0 = __floats2half2_rn(v.x, v.y);
        __half2 p1 = __floats2half2_rn(v.z, v.w);
        uint2 pp;
        pp.x = *reinterpret_cast<unsigned*>(&p0);
        pp.y = *reinterpret_cast<unsigned*>(&p1);
        *(uint2*)(xo + h) = pp;
        const float* g0 = gw + (size_t)h * EEXP;
#pragma unroll
        for (int e = 0; e < EEXP; e++) acc[e] = fmaf(v.x, g0[e], acc[e]);
#pragma unroll
        for (int e = 0; e < EEXP; e++) acc[e] = fmaf(v.y, g0[EEXP + e], acc[e]);
#pragma unroll
        for (int e = 0; e < EEXP; e++) acc[e] = fmaf(v.z, g0[2 * EEXP + e], acc[e]);
#pragma unroll
        for (int e = 0; e < EEXP; e++) acc[e] = fmaf(v.w, g0[3 * EEXP + e], acc[e]);
    }
#pragma unroll
    for (int off = 16; off > 0; off >>= 1) {
#pragma unroll
        for (int e = 0; e < EEXP; e++)
            acc[e] += __shfl_down_sync(0xffffffffu, acc[e], off);
    }
    if (lane == 0) {
        float mx = acc[0];
#pragma unroll
        for (int e = 1; e < EEXP; e++) mx = fmaxf(mx, acc[e]);
        float p[EEXP];
        float s = 0.f;
#pragma unroll
        for (int e = 0; e < EEXP; e++) { p[e] = expf(acc[e] - mx); s += p[e]; }
        float inv = 1.f / s;
#pragma unroll
        for (int e = 0; e < EEXP; e++) p[e] *= inv;
        int e0 = 0;
#pragma unroll
        for (int e = 1; e < EEXP; e++) if (p[e] > p[e0]) e0 = e;
        int e1 = (e0 == 0) ? 1 : 0;
#pragma unroll
        for (int e = 0; e < EEXP; e++) if (e != e0 && p[e] > p[e1]) e1 = e;
        float w0 = p[e0], w1 = p[e1];
        float rs = 1.f / (w0 + w1);
        g_toke[2 * t] = e0;      g_toke[2 * t + 1] = e1;
        g_selw[2 * t] = w0;      g_selw[2 * t + 1] = w1;
        g_tokw[2 * t] = w0 * rs; g_tokw[2 * t + 1] = w1 * rs;
        int p0 = atomicAdd(&g_cnt[e0], 1);
        g_pairs[e0 * NTOK + p0] = 2 * t;
        int p1 = atomicAdd(&g_cnt[e1], 1);
        g_pairs[e1 * NTOK + p1] = 2 * t + 1;
    }
}

// ---------------- aux loss: parallel deterministic two-stage reduction ----------------
__global__ void aux_partial_kernel() {
    __shared__ float sw[256];
    __shared__ int   se[256];
    int tid = threadIdx.x;
    int a = blockIdx.x * 256 + tid;     // AUXB*256 == NTOK*2
    sw[tid] = g_selw[a];
    se[tid] = g_toke[a];
    __syncthreads();
    int w = tid >> 5;                   // warp w handles expert w
    int lane = tid & 31;
    float sumw = 0.f, sumc = 0.f;
#pragma unroll
    for (int i = 0; i < 8; i++) {
        int j = i * 32 + lane;          // fixed order
        if (se[j] == w) { sumw += sw[j]; sumc += 1.f; }
    }
#pragma unroll
    for (int off = 16; off > 0; off >>= 1) {
        sumw += __shfl_down_sync(0xffffffffu, sumw, off);
        sumc += __shfl_down_sync(0xffffffffu, sumc, off);
    }
    if (lane == 0) {
        g_auxw[blockIdx.x * EEXP + w] = sumw;
        g_auxc[blockIdx.x * EEXP + w] = sumc;
    }
}

__global__ void aux_final_kernel(float* __restrict__ out_aux) {
    __shared__ float pe[EEXP], pc[EEXP];
    int tid = threadIdx.x;
    if (tid < EEXP) {
        float sw = 0.f, sc = 0.f;
        for (int b = 0; b < AUXB; b++) {       // fixed order
            sw += g_auxw[b * EEXP + tid];
            sc += g_auxc[b * EEXP + tid];
        }
        pe[tid] = sw;
        pc[tid] = sc;
    }
    __syncthreads();
    if (tid == 0) {
        float aux = 0.f;
#pragma unroll
        for (int e = 0; e < EEXP; e++)
            aux += (pe[e] / (float)NTOK) * (pc[e] / (float)(NTOK * TOPK));
        aux *= (float)EEXP * 1e-3f;
        *out_aux = aux;
    }
}

// ---------------- gate+up GEMM (fp16, 128x128 tile, ldmatrix + cp.async) ----------------
__global__ __launch_bounds__(256) void gateup_kernel() {
    extern __shared__ char sm[];
    int e = blockIdx.z;
    int M = g_cnt[e];
    int m0 = blockIdx.y * TM;
    if (m0 >= M) return;
    int n0 = blockIdx.x * TN;

    int* prow = (int*)sm;
    int* toks = (int*)(sm + 512);
    __half* Ah = (__half*)(sm + 1024);
    __half* Bg = Ah + 2 * TM * AP;
    __half* Bu = Bg + 2 * TM * AP;

    int tid = threadIdx.x;
    if (tid < TM) {
        int r = m0 + tid;
        int pr = (r < M) ? g_pairs[e * NTOK + r] : g_pairs[e * NTOK];
        prow[tid] = pr;
        toks[tid] = pr >> 1;
    }
    __syncthreads();

    const __half* wg = g_wg + (size_t)e * IDIM * HDIM;
    const __half* wu = g_wu + (size_t)e * IDIM * HDIM;

    int wid = tid >> 5;
    int lane = tid & 31;
    int wm = wid >> 1;          // 0..3: 32 rows each
    int wn = wid & 1;           // 0..1: 64 cols each
    int g = lane >> 2;
    int q = lane & 3;

    int arow = tid >> 2;        // 0..63
    int achk = (tid & 3) * 8;

    unsigned offA0 = (unsigned)toks[arow] * HDIM + achk;
    unsigned offA1 = (unsigned)toks[arow + 64] * HDIM + achk;
    unsigned offB0 = (unsigned)(n0 + arow) * HDIM + achk;
    unsigned offB1 = (unsigned)(n0 + arow + 64) * HDIM + achk;

    unsigned aoff[2];
#pragma unroll
    for (int mf = 0; mf < 2; mf++)
        aoff[mf] = ((wm * 32 + mf * 16 + (lane & 15)) * AP + ((lane >> 4) << 3)) * 2;
    unsigned boff[4];
#pragma unroll
    for (int nfp = 0; nfp < 4; nfp++)
        boff[nfp] = ((wn * 64 + nfp * 16 + ((lane >> 4) << 3) + (lane & 7)) * AP
                     + (((lane >> 3) & 1) << 3)) * 2;

    unsigned sAh = (unsigned)__cvta_generic_to_shared(Ah);
    unsigned sBg = (unsigned)__cvta_generic_to_shared(Bg);
    unsigned sBu = (unsigned)__cvta_generic_to_shared(Bu);
    const unsigned str = TM * AP * 2;

    float accG[2][8][4], accU[2][8][4];
#pragma unroll
    for (int i = 0; i < 2; i++)
#pragma unroll
        for (int j = 0; j < 8; j++)
#pragma unroll
            for (int c = 0; c < 4; c++) { accG[i][j][c] = 0.f; accU[i][j][c] = 0.f; }

#define GU_LOAD(st, k0)                                                    \
    do {                                                                   \
        __half* a = Ah + (st) * TM * AP;                                   \
        __half* bg = Bg + (st) * TM * AP;                                  \
        __half* bu = Bu + (st) * TM * AP;                                  \
        cpa16(a + arow * AP + achk,        g_xh + offA0 + (k0));           \
        cpa16(a + (arow + 64) * AP + achk, g_xh + offA1 + (k0));           \
        cpa16(bg + arow * AP + achk,        wg + offB0 + (k0));            \
        cpa16(bg + (arow + 64) * AP + achk, wg + offB1 + (k0));            \
        cpa16(bu + arow * AP + achk,        wu + offB0 + (k0));            \
        cpa16(bu + (arow + 64) * AP + achk, wu + offB1 + (k0));            \
        cpa_commit();                                                      \
    } while (0)

    GU_LOAD(0, 0);

    const int NIT = HDIM / TK;
    for (int it = 0; it < NIT; it++) {
        cpa_wait0();
        __syncthreads();
        if (it + 1 < NIT) GU_LOAD((it + 1) & 1, (it + 1) * TK);
        unsigned st = (it & 1) * str;

#pragma unroll
        for (int kk = 0; kk < TK; kk += 16) {
            unsigned aH[2][4];
#pragma unroll
            for (int mf = 0; mf < 2; mf++)
                ldsm4(aH[mf][0], aH[mf][1], aH[mf][2], aH[mf][3], sAh + st + aoff[mf] + kk * 2);
#pragma unroll
            for (int nfp = 0; nfp < 4; nfp++) {
                unsigned bG[4];
                ldsm4(bG[0], bG[1], bG[2], bG[3], sBg + st + boff[nfp] + kk * 2);
#pragma unroll
                for (int h2 = 0; h2 < 2; h2++) {
                    int nf = nfp * 2 + h2;
#pragma unroll
                    for (int mf = 0; mf < 2; mf++)
                        mma_f16(accG[mf][nf], aH[mf], &bG[h2 * 2]);
                }
            }
#pragma unroll
            for (int nfp = 0; nfp < 4; nfp++) {
                unsigned bU[4];
                ldsm4(bU[0], bU[1], bU[2], bU[3], sBu + st + boff[nfp] + kk * 2);
#pragma unroll
                for (int h2 = 0; h2 < 2; h2++) {
                    int nf = nfp * 2 + h2;
#pragma unroll
                    for (int mf = 0; mf < 2; mf++)
                        mma_f16(accU[mf][nf], aH[mf], &bU[h2 * 2]);
                }
            }
        }
    }
#undef GU_LOAD

    // epilogue: h = silu(g) * u, single-rounded fp16
#pragma unroll
    for (int mf = 0; mf < 2; mf++) {
#pragma unroll
        for (int half = 0; half < 2; half++) {
            int lr = wm * 32 + mf * 16 + g + half * 8;
            int r = m0 + lr;
            if (r < M) {
                int p = prow[lr];
#pragma unroll
                for (int nf = 0; nf < 8; nf++) {
                    int col = n0 + wn * 64 + nf * 8 + 2 * q;
                    float gv0 = accG[mf][nf][half * 2 + 0];
                    float gv1 = accG[mf][nf][half * 2 + 1];
                    float uv0 = accU[mf][nf][half * 2 + 0];
                    float uv1 = accU[mf][nf][half * 2 + 1];
                    float hx = (gv0 / (1.f + expf(-gv0))) * uv0;
                    float hy = (gv1 / (1.f + expf(-gv1))) * uv1;
                    __half2 hv = __floats2half2_rn(hx, hy);
                    *(unsigned*)&g_hb[(size_t)p * IDIM + col] =
                        *reinterpret_cast<unsigned*>(&hv);
                }
            }
        }
    }
}

// ---------------- down GEMM (fp16, 128x128 tile; fused weighted atomic combine) ----------------
__global__ __launch_bounds__(256) void down_kernel(float* __restrict__ y) {
    int e = blockIdx.z;
    int M = g_cnt[e];
    int m0 = blockIdx.y * TM;
    if (m0 >= M) return;
    int n0 = blockIdx.x * TN;

    __shared__ __half Ah[2][TM][AP];
    __shared__ __half Bs[2][TN][AP];
    __shared__ int prow[TM];

    int tid = threadIdx.x;
    if (tid < TM) {
        int r = m0 + tid;
        prow[tid] = (r < M) ? g_pairs[e * NTOK + r] : g_pairs[e * NTOK];
    }
    __syncthreads();

    const __half* wd = g_wd + (size_t)e * HDIM * IDIM;

    int wid = tid >> 5;
    int lane = tid & 31;
    int wm = wid >> 1;
    int wn = wid & 1;
    int g = lane >> 2;
    int q = lane & 3;

    int arow = tid >> 2;
    int achk = (tid & 3) * 8;

    unsigned offA0 = (unsigned)prow[arow] * IDIM + achk;
    unsigned offA1 = (unsigned)prow[arow + 64] * IDIM + achk;
    unsigned offB0 = (unsigned)(n0 + arow) * IDIM + achk;
    unsigned offB1 = (unsigned)(n0 + arow + 64) * IDIM + achk;

    unsigned aoff[2];
#pragma unroll
    for (int mf = 0; mf < 2; mf++)
        aoff[mf] = ((wm * 32 + mf * 16 + (lane & 15)) * AP + ((lane >> 4) << 3)) * 2;
    unsigned boff[4];
#pragma unroll
    for (int nfp = 0; nfp < 4; nfp++)
        boff[nfp] = ((wn * 64 + nfp * 16 + ((lane >> 4) << 3) + (lane & 7)) * AP
                     + (((lane >> 3) & 1) << 3)) * 2;

    unsigned sAh = (unsigned)__cvta_generic_to_shared(&Ah[0][0][0]);
    unsigned sBs = (unsigned)__cvta_generic_to_shared(&Bs[0][0][0]);
    const unsigned str = TM * AP * 2;

    float acc[2][8][4];
#pragma unroll
    for (int i = 0; i < 2; i++)
#pragma unroll
        for (int j = 0; j < 8; j++)
#pragma unroll
            for (int c = 0; c < 4; c++) acc[i][j][c] = 0.f;

#define DN_LOAD(st, k0)                                                    \
    do {                                                                   \
        cpa16(&Ah[st][arow][achk],      g_hb + offA0 + (k0));              \
        cpa16(&Ah[st][arow + 64][achk], g_hb + offA1 + (k0));              \
        cpa16(&Bs[st][arow][achk],      wd + offB0 + (k0));                \
        cpa16(&Bs[st][arow + 64][achk], wd + offB1 + (k0));                \
        cpa_commit();                                                      \
    } while (0)

    DN_LOAD(0, 0);

    const int NIT = IDIM / TK;
    for (int it = 0; it < NIT; it++) {
        cpa_wait0();
        __syncthreads();
        if (it + 1 < NIT) DN_LOAD((it + 1) & 1, (it + 1) * TK);
        unsigned st = (it & 1) * str;

#pragma unroll
        for (int kk = 0; kk < TK; kk += 16) {
            unsigned aH[2][4];
#pragma unroll
            for (int mf = 0; mf < 2; mf++)
                ldsm4(aH[mf][0], aH[mf][1], aH[mf][2], aH[mf][3], sAh + st + aoff[mf] + kk * 2);
#pragma unroll
            for (int nfp = 0; nfp < 4; nfp++) {
                unsigned bB[4];
                ldsm4(bB[0], bB[1], bB[2], bB[3], sBs + st + boff[nfp] + kk * 2);
#pragma unroll
                for (int h2 = 0; h2 < 2; h2++) {
                    int nf = nfp * 2 + h2;
#pragma unroll
                    for (int mf = 0; mf < 2; mf++)
                        mma_f16(acc[mf][nf], aH[mf], &bB[h2 * 2]);
                }
            }
        }
    }
#undef DN_LOAD

    // epilogue: weighted atomic scatter into y (each element gets exactly 2 adds;
    // fp32 add is commutative -> order-independent, deterministic bits).
#pragma unroll
    for (int mf = 0; mf < 2; mf++) {
#pragma unroll
        for (int half = 0; half < 2; half++) {
            int lr = wm * 32 + mf * 16 + g + half * 8;
            int r = m0 + lr;
            if (r < M) {
                int p = prow[lr];
                float w = g_tokw[p];
                float* yr = y + (size_t)(p >> 1) * HDIM;
#pragma unroll
                for (int nf = 0; nf < 8; nf++) {
                    int col = n0 + wn * 64 + nf * 8 + 2 * q;
                    atomicAdd(&yr[col],     w * acc[mf][nf][half * 2 + 0]);
                    atomicAdd(&yr[col + 1], w * acc[mf][nf][half * 2 + 1]);
                }
            }
        }
    }
}

// ---------------- launch ----------------
extern "C" void kernel_launch(void* const* d_in, const int* in_sizes, int n_in,
                              void* d_out, int out_size) {
    const float* x  = (const float*)d_in[0];
    const float* gw = (const float*)d_in[1];
    const float* wg = (const float*)d_in[2];
    const float* wu = (const float*)d_in[3];
    const float* wd = (const float*)d_in[4];
    float* y = (float*)d_out;

    cudaFuncSetAttribute(gateup_kernel, cudaFuncAttributeMaxDynamicSharedMemorySize, GU_SMEM);

    reset_kernel<<<1, 32>>>();
    zero_y_kernel<<<(NTOK * HDIM / 4) / 256, 256>>>(y);
    router_kernel<<<NTOK / 8, 256>>>(x, gw);
    aux_partial_kernel<<<AUXB, 256>>>();
    aux_final_kernel<<<1, 32>>>(y + (out_size - 1));

    transpose_half_kernel<0><<<dim3(IDIM / 64, HDIM / 64, EEXP), 256>>>(wg, HDIM, IDIM);
    transpose_half_kernel<1><<<dim3(IDIM / 64, HDIM / 64, EEXP), 256>>>(wu, HDIM, IDIM);
    transpose_half_kernel<2><<<dim3(HDIM / 64, IDIM / 64, EEXP), 256>>>(wd, IDIM, HDIM);

    gateup_kernel<<<dim3(IDIM / TN, (NTOK * 2) / TM, EEXP), 256, GU_SMEM>>>();
    down_kernel<<<dim3(HDIM / TN, (NTOK * 2) / TM, EEXP), 256>>>(y);
}

// round 16
// speedup vs baseline: 1.1893x; 1.1893x over previous
#include <cuda_runtime.h>
#include <cuda_fp16.h>
#include <math.h>

// Problem constants (fixed by setup_inputs)
#define NTOK 8192      // B*S
#define HDIM 1024
#define IDIM 2048
#define EEXP 8
#define TOPK 2

// GEMM tiling
#define TM 128
#define TN 128
#define TK 32
#define AP 40          // padded k-row length (fp16): 80B stride, conflict-free LDSM

#define GU_SMEM (1024 + 3 * 2 * TM * AP * 2)   // prow/toks + Ah,Bg,Bu double-buffered
#define AUXB 64                                 // aux partial blocks

// ---------------- device scratch ----------------
__device__ int   g_cnt[EEXP];
__device__ int   g_pairs[EEXP * NTOK];
__device__ float g_tokw[NTOK * 2];
__device__ int   g_toke[NTOK * 2];
__device__ float g_selw[NTOK * 2];
__device__ float g_auxw[AUXB * EEXP];   // per-block per-expert selw sums
__device__ float g_auxc[AUXB * EEXP];   // per-block per-expert counts

// all GEMM operands single-rounded fp16
__device__ __half g_xh[NTOK * HDIM];
__device__ __half g_wg[EEXP * IDIM * HDIM];   // gate, transposed [e][i][h]
__device__ __half g_wu[EEXP * IDIM * HDIM];   // up, transposed [e][i][h]
__device__ __half g_wd[EEXP * HDIM * IDIM];   // down, transposed [e][h][i]
__device__ __half g_hb[NTOK * 2 * IDIM];      // silu(g)*u (fp16)  [pair][I]

// ---------------- helpers ----------------
__device__ __forceinline__ void mma_f16(float *d, const unsigned *a, const unsigned *b) {
    asm volatile("mma.sync.aligned.m16n8k16.row.col.f32.f16.f16.f32 "
        "{%0,%1,%2,%3}, {%4,%5,%6,%7}, {%8,%9}, {%0,%1,%2,%3};\n"
        : "+f"(d[0]), "+f"(d[1]), "+f"(d[2]), "+f"(d[3])
        : "r"(a[0]), "r"(a[1]), "r"(a[2]), "r"(a[3]), "r"(b[0]), "r"(b[1]));
}

__device__ __forceinline__ void ldsm4(unsigned &r0, unsigned &r1, unsigned &r2, unsigned &r3,
                                      unsigned a) {
    asm volatile("ldmatrix.sync.aligned.m8n8.x4.shared.b16 {%0,%1,%2,%3}, [%4];\n"
        : "=r"(r0), "=r"(r1), "=r"(r2), "=r"(r3) : "r"(a));
}

__device__ __forceinline__ void cpa16(void* smem, const void* g) {
    unsigned s = (unsigned)__cvta_generic_to_shared(smem);
    asm volatile("cp.async.cg.shared.global [%0], [%1], 16;\n" :: "r"(s), "l"(g));
}
__device__ __forceinline__ void cpa_commit() {
    asm volatile("cp.async.commit_group;\n");
}
__device__ __forceinline__ void cpa_wait0() {
    asm volatile("cp.async.wait_group 0;\n");
}

// ---------------- reset ----------------
__global__ void reset_kernel() {
    if (threadIdx.x < EEXP) g_cnt[threadIdx.x] = 0;
}

// ---------------- zero output (d_out is poisoned; atomics need 0 base) ----------------
__global__ void zero_y_kernel(float* __restrict__ y) {
    int idx = blockIdx.x * blockDim.x + threadIdx.x;
    float4 z; z.x = 0.f; z.y = 0.f; z.z = 0.f; z.w = 0.f;
    ((float4*)y)[idx] = z;
}

// ---------------- transpose weights to fp16: src [E][R][C] -> dst [E][C][R] ----------------
// 64x64 tiles; float4 loads; uint4 (8-half) vectorized transposed stores.
// W selects destinations IN DEVICE CODE (never pass __device__ globals from host:
// that passes the host shadow symbol; ATS silently dereferences host memory).
template<int W>
__global__ void transpose_half_kernel(const float* __restrict__ src, int R, int C) {
    __half* dh = (W == 0) ? g_wg : (W == 1) ? g_wu : g_wd;
    __shared__ float s[64][65];
    int e = blockIdx.z;
    int r0 = blockIdx.y * 64, c0 = blockIdx.x * 64;
    int tid = threadIdx.x;
    const float* sp = src + ((size_t)e * R + r0) * C + c0;
#pragma unroll
    for (int k = 0; k < 4; k++) {
        int u = tid + k * 256;
        int row = u >> 4;
        int cq = (u & 15) * 4;
        float4 v = *(const float4*)(sp + (size_t)row * C + cq);
        s[row][cq + 0] = v.x; s[row][cq + 1] = v.y;
        s[row][cq + 2] = v.z; s[row][cq + 3] = v.w;
    }
    __syncthreads();
    size_t dbase = ((size_t)e * C + c0) * R + r0;
#pragma unroll
    for (int k = 0; k < 2; k++) {
        int u = tid + k * 256;
        int c = u >> 3;
        int rc = (u & 7) * 8;
        __half2 p0 = __floats2half2_rn(s[rc + 0][c], s[rc + 1][c]);
        __half2 p1 = __floats2half2_rn(s[rc + 2][c], s[rc + 3][c]);
        __half2 p2 = __floats2half2_rn(s[rc + 4][c], s[rc + 5][c]);
        __half2 p3 = __floats2half2_rn(s[rc + 6][c], s[rc + 7][c]);
        uint4 o;
        o.x = *reinterpret_cast<unsigned*>(&p0);
        o.y = *reinterpret_cast<unsigned*>(&p1);
        o.z = *reinterpret_cast<unsigned*>(&p2);
        o.w = *reinterpret_cast<unsigned*>(&p3);
        *(uint4*)(dh + dbase + (size_t)c * R + rc) = o;
    }
}

// ---------------- router: one warp per token (also emits x as fp16) ----------------
__global__ void router_kernel(const float* __restrict__ x,
                              const float* __restrict__ gw) {
    int t = blockIdx.x * (blockDim.x >> 5) + (threadIdx.x >> 5);
    int lane = threadIdx.x & 31;
    if (t >= NTOK) return;
    const float* xr = x + (size_t)t * HDIM;
    __half* xo = g_xh + (size_t)t * HDIM;
    float acc[EEXP];
#pragma unroll
    for (int e = 0; e < EEXP; e++) acc[e] = 0.f;
    for (int h = lane; h < HDIM; h += 32) {
        float xv = xr[h];
        xo[h] = __float2half(xv);
        const float* g = gw + h * EEXP;
#pragma unroll
        for (int e = 0; e < EEXP; e++) acc[e] = fmaf(xv, g[e], acc[e]);
    }
#pragma unroll
    for (int off = 16; off > 0; off >>= 1) {
#pragma unroll
        for (int e = 0; e < EEXP; e++)
            acc[e] += __shfl_down_sync(0xffffffffu, acc[e], off);
    }
    if (lane == 0) {
        float mx = acc[0];
#pragma unroll
        for (int e = 1; e < EEXP; e++) mx = fmaxf(mx, acc[e]);
        float p[EEXP];
        float s = 0.f;
#pragma unroll
        for (int e = 0; e < EEXP; e++) { p[e] = expf(acc[e] - mx); s += p[e]; }
        float inv = 1.f / s;
#pragma unroll
        for (int e = 0; e < EEXP; e++) p[e] *= inv;
        int e0 = 0;
#pragma unroll
        for (int e = 1; e < EEXP; e++) if (p[e] > p[e0]) e0 = e;
        int e1 = (e0 == 0) ? 1 : 0;
#pragma unroll
        for (int e = 0; e < EEXP; e++) if (e != e0 && p[e] > p[e1]) e1 = e;
        float w0 = p[e0], w1 = p[e1];
        float rs = 1.f / (w0 + w1);
        g_toke[2 * t] = e0;      g_toke[2 * t + 1] = e1;
        g_selw[2 * t] = w0;      g_selw[2 * t + 1] = w1;
        g_tokw[2 * t] = w0 * rs; g_tokw[2 * t + 1] = w1 * rs;
        int p0 = atomicAdd(&g_cnt[e0], 1);
        g_pairs[e0 * NTOK + p0] = 2 * t;
        int p1 = atomicAdd(&g_cnt[e1], 1);
        g_pairs[e1 * NTOK + p1] = 2 * t + 1;
    }
}

// ---------------- aux loss: parallel deterministic two-stage reduction ----------------
__global__ void aux_partial_kernel() {
    __shared__ float sw[256];
    __shared__ int   se[256];
    int tid = threadIdx.x;
    int a = blockIdx.x * 256 + tid;     // AUXB*256 == NTOK*2
    sw[tid] = g_selw[a];
    se[tid] = g_toke[a];
    __syncthreads();
    int w = tid >> 5;                   // warp w handles expert w
    int lane = tid & 31;
    float sumw = 0.f, sumc = 0.f;
#pragma unroll
    for (int i = 0; i < 8; i++) {
        int j = i * 32 + lane;          // fixed order
        if (se[j] == w) { sumw += sw[j]; sumc += 1.f; }
    }
#pragma unroll
    for (int off = 16; off > 0; off >>= 1) {
        sumw += __shfl_down_sync(0xffffffffu, sumw, off);
        sumc += __shfl_down_sync(0xffffffffu, sumc, off);
    }
    if (lane == 0) {
        g_auxw[blockIdx.x * EEXP + w] = sumw;
        g_auxc[blockIdx.x * EEXP + w] = sumc;
    }
}

__global__ void aux_final_kernel(float* __restrict__ out_aux) {
    __shared__ float pe[EEXP], pc[EEXP];
    int tid = threadIdx.x;
    if (tid < EEXP) {
        float sw = 0.f, sc = 0.f;
        for (int b = 0; b < AUXB; b++) {       // fixed order
            sw += g_auxw[b * EEXP + tid];
            sc += g_auxc[b * EEXP + tid];
        }
        pe[tid] = sw;
        pc[tid] = sc;
    }
    __syncthreads();
    if (tid == 0) {
        float aux = 0.f;
#pragma unroll
        for (int e = 0; e < EEXP; e++)
            aux += (pe[e] / (float)NTOK) * (pc[e] / (float)(NTOK * TOPK));
        aux *= (float)EEXP * 1e-3f;
        *out_aux = aux;
    }
}

// ---------------- gate+up GEMM (fp16, 128x128 tile, ldmatrix + cp.async) ----------------
__global__ __launch_bounds__(256) void gateup_kernel() {
    extern __shared__ char sm[];
    int e = blockIdx.z;
    int M = g_cnt[e];
    int m0 = blockIdx.y * TM;
    if (m0 >= M) return;
    int n0 = blockIdx.x * TN;

    int* prow = (int*)sm;
    int* toks = (int*)(sm + 512);
    __half* Ah = (__half*)(sm + 1024);
    __half* Bg = Ah + 2 * TM * AP;
    __half* Bu = Bg + 2 * TM * AP;

    int tid = threadIdx.x;
    if (tid < TM) {
        int r = m0 + tid;
        int pr = (r < M) ? g_pairs[e * NTOK + r] : g_pairs[e * NTOK];
        prow[tid] = pr;
        toks[tid] = pr >> 1;
    }
    __syncthreads();

    const __half* wg = g_wg + (size_t)e * IDIM * HDIM;
    const __half* wu = g_wu + (size_t)e * IDIM * HDIM;

    int wid = tid >> 5;
    int lane = tid & 31;
    int wm = wid >> 1;          // 0..3: 32 rows each
    int wn = wid & 1;           // 0..1: 64 cols each
    int g = lane >> 2;
    int q = lane & 3;

    int arow = tid >> 2;        // 0..63
    int achk = (tid & 3) * 8;

    unsigned offA0 = (unsigned)toks[arow] * HDIM + achk;
    unsigned offA1 = (unsigned)toks[arow + 64] * HDIM + achk;
    unsigned offB0 = (unsigned)(n0 + arow) * HDIM + achk;
    unsigned offB1 = (unsigned)(n0 + arow + 64) * HDIM + achk;

    unsigned aoff[2];
#pragma unroll
    for (int mf = 0; mf < 2; mf++)
        aoff[mf] = ((wm * 32 + mf * 16 + (lane & 15)) * AP + ((lane >> 4) << 3)) * 2;
    unsigned boff[4];
#pragma unroll
    for (int nfp = 0; nfp < 4; nfp++)
        boff[nfp] = ((wn * 64 + nfp * 16 + ((lane >> 4) << 3) + (lane & 7)) * AP
                     + (((lane >> 3) & 1) << 3)) * 2;

    unsigned sAh = (unsigned)__cvta_generic_to_shared(Ah);
    unsigned sBg = (unsigned)__cvta_generic_to_shared(Bg);
    unsigned sBu = (unsigned)__cvta_generic_to_shared(Bu);
    const unsigned str = TM * AP * 2;

    float accG[2][8][4], accU[2][8][4];
#pragma unroll
    for (int i = 0; i < 2; i++)
#pragma unroll
        for (int j = 0; j < 8; j++)
#pragma unroll
            for (int c = 0; c < 4; c++) { accG[i][j][c] = 0.f; accU[i][j][c] = 0.f; }

#define GU_LOAD(st, k0)                                                    \
    do {                                                                   \
        __half* a = Ah + (st) * TM * AP;                                   \
        __half* bg = Bg + (st) * TM * AP;                                  \
        __half* bu = Bu + (st) * TM * AP;                                  \
        cpa16(a + arow * AP + achk,        g_xh + offA0 + (k0));           \
        cpa16(a + (arow + 64) * AP + achk, g_xh + offA1 + (k0));           \
        cpa16(bg + arow * AP + achk,        wg + offB0 + (k0));            \
        cpa16(bg + (arow + 64) * AP + achk, wg + offB1 + (k0));            \
        cpa16(bu + arow * AP + achk,        wu + offB0 + (k0));            \
        cpa16(bu + (arow + 64) * AP + achk, wu + offB1 + (k0));            \
        cpa_commit();                                                      \
    } while (0)

    GU_LOAD(0, 0);

    const int NIT = HDIM / TK;
    for (int it = 0; it < NIT; it++) {
        cpa_wait0();
        __syncthreads();
        if (it + 1 < NIT) GU_LOAD((it + 1) & 1, (it + 1) * TK);
        unsigned st = (it & 1) * str;

#pragma unroll
        for (int kk = 0; kk < TK; kk += 16) {
            unsigned aH[2][4];
#pragma unroll
            for (int mf = 0; mf < 2; mf++)
                ldsm4(aH[mf][0], aH[mf][1], aH[mf][2], aH[mf][3], sAh + st + aoff[mf] + kk * 2);
#pragma unroll
            for (int nfp = 0; nfp < 4; nfp++) {
                unsigned bG[4];
                ldsm4(bG[0], bG[1], bG[2], bG[3], sBg + st + boff[nfp] + kk * 2);
#pragma unroll
                for (int h2 = 0; h2 < 2; h2++) {
                    int nf = nfp * 2 + h2;
#pragma unroll
                    for (int mf = 0; mf < 2; mf++)
                        mma_f16(accG[mf][nf], aH[mf], &bG[h2 * 2]);
                }
            }
#pragma unroll
            for (int nfp = 0; nfp < 4; nfp++) {
                unsigned bU[4];
                ldsm4(bU[0], bU[1], bU[2], bU[3], sBu + st + boff[nfp] + kk * 2);
#pragma unroll
                for (int h2 = 0; h2 < 2; h2++) {
                    int nf = nfp * 2 + h2;
#pragma unroll
                    for (int mf = 0; mf < 2; mf++)
                        mma_f16(accU[mf][nf], aH[mf], &bU[h2 * 2]);
                }
            }
        }
    }
#undef GU_LOAD

    // epilogue: h = silu(g) * u, single-rounded fp16
#pragma unroll
    for (int mf = 0; mf < 2; mf++) {
#pragma unroll
        for (int half = 0; half < 2; half++) {
            int lr = wm * 32 + mf * 16 + g + half * 8;
            int r = m0 + lr;
            if (r < M) {
                int p = prow[lr];
#pragma unroll
                for (int nf = 0; nf < 8; nf++) {
                    int col = n0 + wn * 64 + nf * 8 + 2 * q;
                    float gv0 = accG[mf][nf][half * 2 + 0];
                    float gv1 = accG[mf][nf][half * 2 + 1];
                    float uv0 = accU[mf][nf][half * 2 + 0];
                    float uv1 = accU[mf][nf][half * 2 + 1];
                    float hx = (gv0 / (1.f + expf(-gv0))) * uv0;
                    float hy = (gv1 / (1.f + expf(-gv1))) * uv1;
                    __half2 hv = __floats2half2_rn(hx, hy);
                    *(unsigned*)&g_hb[(size_t)p * IDIM + col] =
                        *reinterpret_cast<unsigned*>(&hv);
                }
            }
        }
    }
}

// ---------------- down GEMM (fp16, 128x128 tile; fused weighted atomic combine) ----------------
__global__ __launch_bounds__(256) void down_kernel(float* __restrict__ y) {
    int e = blockIdx.z;
    int M = g_cnt[e];
    int m0 = blockIdx.y * TM;
    if (m0 >= M) return;
    int n0 = blockIdx.x * TN;

    __shared__ __half Ah[2][TM][AP];
    __shared__ __half Bs[2][TN][AP];
    __shared__ int prow[TM];

    int tid = threadIdx.x;
    if (tid < TM) {
        int r = m0 + tid;
        prow[tid] = (r < M) ? g_pairs[e * NTOK + r] : g_pairs[e * NTOK];
    }
    __syncthreads();

    const __half* wd = g_wd + (size_t)e * HDIM * IDIM;

    int wid = tid >> 5;
    int lane = tid & 31;
    int wm = wid >> 1;
    int wn = wid & 1;
    int g = lane >> 2;
    int q = lane & 3;

    int arow = tid >> 2;
    int achk = (tid & 3) * 8;

    unsigned offA0 = (unsigned)prow[arow] * IDIM + achk;
    unsigned offA1 = (unsigned)prow[arow + 64] * IDIM + achk;
    unsigned offB0 = (unsigned)(n0 + arow) * IDIM + achk;
    unsigned offB1 = (unsigned)(n0 + arow + 64) * IDIM + achk;

    unsigned aoff[2];
#pragma unroll
    for (int mf = 0; mf < 2; mf++)
        aoff[mf] = ((wm * 32 + mf * 16 + (lane & 15)) * AP + ((lane >> 4) << 3)) * 2;
    unsigned boff[4];
#pragma unroll
    for (int nfp = 0; nfp < 4; nfp++)
        boff[nfp] = ((wn * 64 + nfp * 16 + ((lane >> 4) << 3) + (lane & 7)) * AP
                     + (((lane >> 3) & 1) << 3)) * 2;

    unsigned sAh = (unsigned)__cvta_generic_to_shared(&Ah[0][0][0]);
    unsigned sBs = (unsigned)__cvta_generic_to_shared(&Bs[0][0][0]);
    const unsigned str = TM * AP * 2;

    float acc[2][8][4];
#pragma unroll
    for (int i = 0; i < 2; i++)
#pragma unroll
        for (int j = 0; j < 8; j++)
#pragma unroll
            for (int c = 0; c < 4; c++) acc[i][j][c] = 0.f;

#define DN_LOAD(st, k0)                                                    \
    do {                                                                   \
        cpa16(&Ah[st][arow][achk],      g_hb + offA0 + (k0));              \
        cpa16(&Ah[st][arow + 64][achk], g_hb + offA1 + (k0));              \
        cpa16(&Bs[st][arow][achk],      wd + offB0 + (k0));                \
        cpa16(&Bs[st][arow + 64][achk], wd + offB1 + (k0));                \
        cpa_commit();                                                      \
    } while (0)

    DN_LOAD(0, 0);

    const int NIT = IDIM / TK;
    for (int it = 0; it < NIT; it++) {
        cpa_wait0();
        __syncthreads();
        if (it + 1 < NIT) DN_LOAD((it + 1) & 1, (it + 1) * TK);
        unsigned st = (it & 1) * str;

#pragma unroll
        for (int kk = 0; kk < TK; kk += 16) {
            unsigned aH[2][4];
#pragma unroll
            for (int mf = 0; mf < 2; mf++)
                ldsm4(aH[mf][0], aH[mf][1], aH[mf][2], aH[mf][3], sAh + st + aoff[mf] + kk * 2);
#pragma unroll
            for (int nfp = 0; nfp < 4; nfp++) {
                unsigned bB[4];
                ldsm4(bB[0], bB[1], bB[2], bB[3], sBs + st + boff[nfp] + kk * 2);
#pragma unroll
                for (int h2 = 0; h2 < 2; h2++) {
                    int nf = nfp * 2 + h2;
#pragma unroll
                    for (int mf = 0; mf < 2; mf++)
                        mma_f16(acc[mf][nf], aH[mf], &bB[h2 * 2]);
                }
            }
        }
    }
#undef DN_LOAD

    // epilogue: weighted atomic scatter into y (each element gets exactly 2 adds;
    // fp32 add is commutative -> order-independent, deterministic bits).
#pragma unroll
    for (int mf = 0; mf < 2; mf++) {
#pragma unroll
        for (int half = 0; half < 2; half++) {
            int lr = wm * 32 + mf * 16 + g + half * 8;
            int r = m0 + lr;
            if (r < M) {
                int p = prow[lr];
                float w = g_tokw[p];
                float* yr = y + (size_t)(p >> 1) * HDIM;
#pragma unroll
                for (int nf = 0; nf < 8; nf++) {
                    int col = n0 + wn * 64 + nf * 8 + 2 * q;
                    atomicAdd(&yr[col],     w * acc[mf][nf][half * 2 + 0]);
                    atomicAdd(&yr[col + 1], w * acc[mf][nf][half * 2 + 1]);
                }
            }
        }
    }
}

// ---------------- launch ----------------
extern "C" void kernel_launch(void* const* d_in, const int* in_sizes, int n_in,
                              void* d_out, int out_size) {
    const float* x  = (const float*)d_in[0];
    const float* gw = (const float*)d_in[1];
    const float* wg = (const float*)d_in[2];
    const float* wu = (const float*)d_in[3];
    const float* wd = (const float*)d_in[4];
    float* y = (float*)d_out;

    cudaFuncSetAttribute(gateup_kernel, cudaFuncAttributeMaxDynamicSharedMemorySize, GU_SMEM);

    reset_kernel<<<1, 32>>>();
    zero_y_kernel<<<(NTOK * HDIM / 4) / 256, 256>>>(y);
    router_kernel<<<NTOK / 8, 256>>>(x, gw);
    aux_partial_kernel<<<AUXB, 256>>>();
    aux_final_kernel<<<1, 32>>>(y + (out_size - 1));

    transpose_half_kernel<0><<<dim3(IDIM / 64, HDIM / 64, EEXP), 256>>>(wg, HDIM, IDIM);
    transpose_half_kernel<1><<<dim3(IDIM / 64, HDIM / 64, EEXP), 256>>>(wu, HDIM, IDIM);
    transpose_half_kernel<2><<<dim3(HDIM / 64, IDIM / 64, EEXP), 256>>>(wd, IDIM, HDIM);

    gateup_kernel<<<dim3(IDIM / TN, (NTOK * 2) / TM, EEXP), 256, GU_SMEM>>>();
    down_kernel<<<dim3(HDIM / TN, (NTOK * 2) / TM, EEXP), 256>>>(y);
}

// round 17
// speedup vs baseline: 1.2021x; 1.0107x over previous
#include <cuda_runtime.h>
#include <cuda_fp16.h>
#include <math.h>

// Problem constants (fixed by setup_inputs)
#define NTOK 8192      // B*S
#define HDIM 1024
#define IDIM 2048
#define EEXP 8
#define TOPK 2

// GEMM tiling
#define TM 128
#define TN 128
#define TK 32
#define AP 40          // padded k-row length (fp16): 80B stride, conflict-free LDSM

#define GU_SMEM (1024 + 3 * 2 * TM * AP * 2)   // prow/toks + Ah,Bg,Bu double-buffered
#define AUXB 64                                 // aux partial blocks

// ---------------- device scratch ----------------
__device__ int   g_cnt[EEXP];
__device__ int   g_pairs[EEXP * NTOK];
__device__ float g_tokw[NTOK * 2];
__device__ int   g_toke[NTOK * 2];
__device__ float g_selw[NTOK * 2];
__device__ float g_auxw[AUXB * EEXP];   // per-block per-expert selw sums
__device__ float g_auxc[AUXB * EEXP];   // per-block per-expert counts

// all GEMM operands single-rounded fp16
__device__ __half g_xh[NTOK * HDIM];
__device__ __half g_wg[EEXP * IDIM * HDIM];   // gate, transposed [e][i][h]
__device__ __half g_wu[EEXP * IDIM * HDIM];   // up, transposed [e][i][h]
__device__ __half g_wd[EEXP * HDIM * IDIM];   // down, transposed [e][h][i]
__device__ __half g_hb[NTOK * 2 * IDIM];      // silu(g)*u (fp16)  [pair][I]

// ---------------- helpers ----------------
__device__ __forceinline__ void mma_f16(float *d, const unsigned *a, const unsigned *b) {
    asm volatile("mma.sync.aligned.m16n8k16.row.col.f32.f16.f16.f32 "
        "{%0,%1,%2,%3}, {%4,%5,%6,%7}, {%8,%9}, {%0,%1,%2,%3};\n"
        : "+f"(d[0]), "+f"(d[1]), "+f"(d[2]), "+f"(d[3])
        : "r"(a[0]), "r"(a[1]), "r"(a[2]), "r"(a[3]), "r"(b[0]), "r"(b[1]));
}

__device__ __forceinline__ void ldsm4(unsigned &r0, unsigned &r1, unsigned &r2, unsigned &r3,
                                      unsigned a) {
    asm volatile("ldmatrix.sync.aligned.m8n8.x4.shared.b16 {%0,%1,%2,%3}, [%4];\n"
        : "=r"(r0), "=r"(r1), "=r"(r2), "=r"(r3) : "r"(a));
}

__device__ __forceinline__ void cpa16(void* smem, const void* g) {
    unsigned s = (unsigned)__cvta_generic_to_shared(smem);
    asm volatile("cp.async.cg.shared.global [%0], [%1], 16;\n" :: "r"(s), "l"(g));
}
__device__ __forceinline__ void cpa_commit() {
    asm volatile("cp.async.commit_group;\n");
}
__device__ __forceinline__ void cpa_wait0() {
    asm volatile("cp.async.wait_group 0;\n");
}

// ---------------- reset ----------------
__global__ void reset_kernel() {
    if (threadIdx.x < EEXP) g_cnt[threadIdx.x] = 0;
}

// ---------------- zero output (d_out is poisoned; atomics need 0 base) ----------------
__global__ void zero_y_kernel(float* __restrict__ y) {
    int idx = blockIdx.x * blockDim.x + threadIdx.x;
    float4 z; z.x = 0.f; z.y = 0.f; z.z = 0.f; z.w = 0.f;
    ((float4*)y)[idx] = z;
}

// ---------------- transpose weights to fp16: src [E][R][C] -> dst [E][C][R] ----------------
// 64x64 tiles; float4 loads; uint4 (8-half) vectorized transposed stores.
// W selects destinations IN DEVICE CODE (never pass __device__ globals from host:
// that passes the host shadow symbol; ATS silently dereferences host memory).
template<int W>
__global__ void transpose_half_kernel(const float* __restrict__ src, int R, int C) {
    __half* dh = (W == 0) ? g_wg : (W == 1) ? g_wu : g_wd;
    __shared__ float s[64][65];
    int e = blockIdx.z;
    int r0 = blockIdx.y * 64, c0 = blockIdx.x * 64;
    int tid = threadIdx.x;
    const float* sp = src + ((size_t)e * R + r0) * C + c0;
#pragma unroll
    for (int k = 0; k < 4; k++) {
        int u = tid + k * 256;
        int row = u >> 4;
        int cq = (u & 15) * 4;
        float4 v = *(const float4*)(sp + (size_t)row * C + cq);
        s[row][cq + 0] = v.x; s[row][cq + 1] = v.y;
        s[row][cq + 2] = v.z; s[row][cq + 3] = v.w;
    }
    __syncthreads();
    size_t dbase = ((size_t)e * C + c0) * R + r0;
#pragma unroll
    for (int k = 0; k < 2; k++) {
        int u = tid + k * 256;
        int c = u >> 3;
        int rc = (u & 7) * 8;
        __half2 p0 = __floats2half2_rn(s[rc + 0][c], s[rc + 1][c]);
        __half2 p1 = __floats2half2_rn(s[rc + 2][c], s[rc + 3][c]);
        __half2 p2 = __floats2half2_rn(s[rc + 4][c], s[rc + 5][c]);
        __half2 p3 = __floats2half2_rn(s[rc + 6][c], s[rc + 7][c]);
        uint4 o;
        o.x = *reinterpret_cast<unsigned*>(&p0);
        o.y = *reinterpret_cast<unsigned*>(&p1);
        o.z = *reinterpret_cast<unsigned*>(&p2);
        o.w = *reinterpret_cast<unsigned*>(&p3);
        *(uint4*)(dh + dbase + (size_t)c * R + rc) = o;
    }
}

// ---------------- router: one warp per token (also emits x as fp16) ----------------
__global__ void router_kernel(const float* __restrict__ x,
                              const float* __restrict__ gw) {
    int t = blockIdx.x * (blockDim.x >> 5) + (threadIdx.x >> 5);
    int lane = threadIdx.x & 31;
    if (t >= NTOK) return;
    const float* xr = x + (size_t)t * HDIM;
    __half* xo = g_xh + (size_t)t * HDIM;
    float acc[EEXP];
#pragma unroll
    for (int e = 0; e < EEXP; e++) acc[e] = 0.f;
    for (int h = lane; h < HDIM; h += 32) {
        float xv = xr[h];
        xo[h] = __float2half(xv);
        const float* g = gw + h * EEXP;
#pragma unroll
        for (int e = 0; e < EEXP; e++) acc[e] = fmaf(xv, g[e], acc[e]);
    }
#pragma unroll
    for (int off = 16; off > 0; off >>= 1) {
#pragma unroll
        for (int e = 0; e < EEXP; e++)
            acc[e] += __shfl_down_sync(0xffffffffu, acc[e], off);
    }
    if (lane == 0) {
        float mx = acc[0];
#pragma unroll
        for (int e = 1; e < EEXP; e++) mx = fmaxf(mx, acc[e]);
        float p[EEXP];
        float s = 0.f;
#pragma unroll
        for (int e = 0; e < EEXP; e++) { p[e] = expf(acc[e] - mx); s += p[e]; }
        float inv = 1.f / s;
#pragma unroll
        for (int e = 0; e < EEXP; e++) p[e] *= inv;
        int e0 = 0;
#pragma unroll
        for (int e = 1; e < EEXP; e++) if (p[e] > p[e0]) e0 = e;
        int e1 = (e0 == 0) ? 1 : 0;
#pragma unroll
        for (int e = 0; e < EEXP; e++) if (e != e0 && p[e] > p[e1]) e1 = e;
        float w0 = p[e0], w1 = p[e1];
        float rs = 1.f / (w0 + w1);
        g_toke[2 * t] = e0;      g_toke[2 * t + 1] = e1;
        g_selw[2 * t] = w0;      g_selw[2 * t + 1] = w1;
        g_tokw[2 * t] = w0 * rs; g_tokw[2 * t + 1] = w1 * rs;
        int p0 = atomicAdd(&g_cnt[e0], 1);
        g_pairs[e0 * NTOK + p0] = 2 * t;
        int p1 = atomicAdd(&g_cnt[e1], 1);
        g_pairs[e1 * NTOK + p1] = 2 * t + 1;
    }
}

// ---------------- aux loss: parallel deterministic two-stage reduction ----------------
__global__ void aux_partial_kernel() {
    __shared__ float sw[256];
    __shared__ int   se[256];
    int tid = threadIdx.x;
    int a = blockIdx.x * 256 + tid;     // AUXB*256 == NTOK*2
    sw[tid] = g_selw[a];
    se[tid] = g_toke[a];
    __syncthreads();
    int w = tid >> 5;                   // warp w handles expert w
    int lane = tid & 31;
    float sumw = 0.f, sumc = 0.f;
#pragma unroll
    for (int i = 0; i < 8; i++) {
        int j = i * 32 + lane;          // fixed order
        if (se[j] == w) { sumw += sw[j]; sumc += 1.f; }
    }
#pragma unroll
    for (int off = 16; off > 0; off >>= 1) {
        sumw += __shfl_down_sync(0xffffffffu, sumw, off);
        sumc += __shfl_down_sync(0xffffffffu, sumc, off);
    }
    if (lane == 0) {
        g_auxw[blockIdx.x * EEXP + w] = sumw;
        g_auxc[blockIdx.x * EEXP + w] = sumc;
    }
}

__global__ void aux_final_kernel(float* __restrict__ out_aux) {
    __shared__ float pe[EEXP], pc[EEXP];
    int tid = threadIdx.x;
    if (tid < EEXP) {
        float sw = 0.f, sc = 0.f;
        for (int b = 0; b < AUXB; b++) {       // fixed order
            sw += g_auxw[b * EEXP + tid];
            sc += g_auxc[b * EEXP + tid];
        }
        pe[tid] = sw;
        pc[tid] = sc;
    }
    __syncthreads();
    if (tid == 0) {
        float aux = 0.f;
#pragma unroll
        for (int e = 0; e < EEXP; e++)
            aux += (pe[e] / (float)NTOK) * (pc[e] / (float)(NTOK * TOPK));
        aux *= (float)EEXP * 1e-3f;
        *out_aux = aux;
    }
}

// ---------------- gate+up GEMM (fp16, 128x128 tile, ldmatrix + cp.async) ----------------
__global__ __launch_bounds__(256) void gateup_kernel() {
    extern __shared__ char sm[];
    int e = blockIdx.z;
    int M = g_cnt[e];
    int m0 = blockIdx.y * TM;
    if (m0 >= M) return;
    int n0 = blockIdx.x * TN;

    int* prow = (int*)sm;
    int* toks = (int*)(sm + 512);
    __half* Ah = (__half*)(sm + 1024);
    __half* Bg = Ah + 2 * TM * AP;
    __half* Bu = Bg + 2 * TM * AP;

    int tid = threadIdx.x;
    if (tid < TM) {
        int r = m0 + tid;
        int pr = (r < M) ? g_pairs[e * NTOK + r] : g_pairs[e * NTOK];
        prow[tid] = pr;
        toks[tid] = pr >> 1;
    }
    __syncthreads();

    const __half* wg = g_wg + (size_t)e * IDIM * HDIM;
    const __half* wu = g_wu + (size_t)e * IDIM * HDIM;

    int wid = tid >> 5;
    int lane = tid & 31;
    int wm = wid >> 1;          // 0..3: 32 rows each
    int wn = wid & 1;           // 0..1: 64 cols each
    int g = lane >> 2;
    int q = lane & 3;

    int arow = tid >> 2;        // 0..63
    int achk = (tid & 3) * 8;

    unsigned offA0 = (unsigned)toks[arow] * HDIM + achk;
    unsigned offA1 = (unsigned)toks[arow + 64] * HDIM + achk;
    unsigned offB0 = (unsigned)(n0 + arow) * HDIM + achk;
    unsigned offB1 = (unsigned)(n0 + arow + 64) * HDIM + achk;

    unsigned aoff[2];
#pragma unroll
    for (int mf = 0; mf < 2; mf++)
        aoff[mf] = ((wm * 32 + mf * 16 + (lane & 15)) * AP + ((lane >> 4) << 3)) * 2;
    unsigned boff[4];
#pragma unroll
    for (int nfp = 0; nfp < 4; nfp++)
        boff[nfp] = ((wn * 64 + nfp * 16 + ((lane >> 4) << 3) + (lane & 7)) * AP
                     + (((lane >> 3) & 1) << 3)) * 2;

    unsigned sAh = (unsigned)__cvta_generic_to_shared(Ah);
    unsigned sBg = (unsigned)__cvta_generic_to_shared(Bg);
    unsigned sBu = (unsigned)__cvta_generic_to_shared(Bu);
    const unsigned str = TM * AP * 2;

    float accG[2][8][4], accU[2][8][4];
#pragma unroll
    for (int i = 0; i < 2; i++)
#pragma unroll
        for (int j = 0; j < 8; j++)
#pragma unroll
            for (int c = 0; c < 4; c++) { accG[i][j][c] = 0.f; accU[i][j][c] = 0.f; }

#define GU_LOAD(st, k0)                                                    \
    do {                                                                   \
        __half* a = Ah + (st) * TM * AP;                                   \
        __half* bg = Bg + (st) * TM * AP;                                  \
        __half* bu = Bu + (st) * TM * AP;                                  \
        cpa16(a + arow * AP + achk,        g_xh + offA0 + (k0));           \
        cpa16(a + (arow + 64) * AP + achk, g_xh + offA1 + (k0));           \
        cpa16(bg + arow * AP + achk,        wg + offB0 + (k0));            \
        cpa16(bg + (arow + 64) * AP + achk, wg + offB1 + (k0));            \
        cpa16(bu + arow * AP + achk,        wu + offB0 + (k0));            \
        cpa16(bu + (arow + 64) * AP + achk, wu + offB1 + (k0));            \
        cpa_commit();                                                      \
    } while (0)

    GU_LOAD(0, 0);

    const int NIT = HDIM / TK;
    for (int it = 0; it < NIT; it++) {
        cpa_wait0();
        __syncthreads();
        if (it + 1 < NIT) GU_LOAD((it + 1) & 1, (it + 1) * TK);
        unsigned st = (it & 1) * str;

#pragma unroll
        for (int kk = 0; kk < TK; kk += 16) {
            unsigned aH[2][4];
#pragma unroll
            for (int mf = 0; mf < 2; mf++)
                ldsm4(aH[mf][0], aH[mf][1], aH[mf][2], aH[mf][3], sAh + st + aoff[mf] + kk * 2);
#pragma unroll
            for (int nfp = 0; nfp < 4; nfp++) {
                unsigned bG[4];
                ldsm4(bG[0], bG[1], bG[2], bG[3], sBg + st + boff[nfp] + kk * 2);
#pragma unroll
                for (int h2 = 0; h2 < 2; h2++) {
                    int nf = nfp * 2 + h2;
#pragma unroll
                    for (int mf = 0; mf < 2; mf++)
                        mma_f16(accG[mf][nf], aH[mf], &bG[h2 * 2]);
                }
            }
#pragma unroll
            for (int nfp = 0; nfp < 4; nfp++) {
                unsigned bU[4];
                ldsm4(bU[0], bU[1], bU[2], bU[3], sBu + st + boff[nfp] + kk * 2);
#pragma unroll
                for (int h2 = 0; h2 < 2; h2++) {
                    int nf = nfp * 2 + h2;
#pragma unroll
                    for (int mf = 0; mf < 2; mf++)
                        mma_f16(accU[mf][nf], aH[mf], &bU[h2 * 2]);
                }
            }
        }
    }
#undef GU_LOAD

    // epilogue: h = silu(g) * u, single-rounded fp16
#pragma unroll
    for (int mf = 0; mf < 2; mf++) {
#pragma unroll
        for (int half = 0; half < 2; half++) {
            int lr = wm * 32 + mf * 16 + g + half * 8;
            int r = m0 + lr;
            if (r < M) {
                int p = prow[lr];
#pragma unroll
                for (int nf = 0; nf < 8; nf++) {
                    int col = n0 + wn * 64 + nf * 8 + 2 * q;
                    float gv0 = accG[mf][nf][half * 2 + 0];
                    float gv1 = accG[mf][nf][half * 2 + 1];
                    float uv0 = accU[mf][nf][half * 2 + 0];
                    float uv1 = accU[mf][nf][half * 2 + 1];
                    float hx = (gv0 / (1.f + expf(-gv0))) * uv0;
                    float hy = (gv1 / (1.f + expf(-gv1))) * uv1;
                    __half2 hv = __floats2half2_rn(hx, hy);
                    *(unsigned*)&g_hb[(size_t)p * IDIM + col] =
                        *reinterpret_cast<unsigned*>(&hv);
                }
            }
        }
    }
}

// ---------------- down GEMM (fp16, 128x128 tile; fused weighted atomic combine) ----------------
__global__ __launch_bounds__(256) void down_kernel(float* __restrict__ y) {
    int e = blockIdx.z;
    int M = g_cnt[e];
    int m0 = blockIdx.y * TM;
    if (m0 >= M) return;
    int n0 = blockIdx.x * TN;

    __shared__ __half Ah[2][TM][AP];
    __shared__ __half Bs[2][TN][AP];
    __shared__ int prow[TM];

    int tid = threadIdx.x;
    if (tid < TM) {
        int r = m0 + tid;
        prow[tid] = (r < M) ? g_pairs[e * NTOK + r] : g_pairs[e * NTOK];
    }
    __syncthreads();

    const __half* wd = g_wd + (size_t)e * HDIM * IDIM;

    int wid = tid >> 5;
    int lane = tid & 31;
    int wm = wid >> 1;
    int wn = wid & 1;
    int g = lane >> 2;
    int q = lane & 3;

    int arow = tid >> 2;
    int achk = (tid & 3) * 8;

    unsigned offA0 = (unsigned)prow[arow] * IDIM + achk;
    unsigned offA1 = (unsigned)prow[arow + 64] * IDIM + achk;
    unsigned offB0 = (unsigned)(n0 + arow) * IDIM + achk;
    unsigned offB1 = (unsigned)(n0 + arow + 64) * IDIM + achk;

    unsigned aoff[2];
#pragma unroll
    for (int mf = 0; mf < 2; mf++)
        aoff[mf] = ((wm * 32 + mf * 16 + (lane & 15)) * AP + ((lane >> 4) << 3)) * 2;
    unsigned boff[4];
#pragma unroll
    for (int nfp = 0; nfp < 4; nfp++)
        boff[nfp] = ((wn * 64 + nfp * 16 + ((lane >> 4) << 3) + (lane & 7)) * AP
                     + (((lane >> 3) & 1) << 3)) * 2;

    unsigned sAh = (unsigned)__cvta_generic_to_shared(&Ah[0][0][0]);
    unsigned sBs = (unsigned)__cvta_generic_to_shared(&Bs[0][0][0]);
    const unsigned str = TM * AP * 2;

    float acc[2][8][4];
#pragma unroll
    for (int i = 0; i < 2; i++)
#pragma unroll
        for (int j = 0; j < 8; j++)
#pragma unroll
            for (int c = 0; c < 4; c++) acc[i][j][c] = 0.f;

#define DN_LOAD(st, k0)                                                    \
    do {                                                                   \
        cpa16(&Ah[st][arow][achk],      g_hb + offA0 + (k0));              \
        cpa16(&Ah[st][arow + 64][achk], g_hb + offA1 + (k0));              \
        cpa16(&Bs[st][arow][achk],      wd + offB0 + (k0));                \
        cpa16(&Bs[st][arow + 64][achk], wd + offB1 + (k0));                \
        cpa_commit();                                                      \
    } while (0)

    DN_LOAD(0, 0);

    const int NIT = IDIM / TK;
    for (int it = 0; it < NIT; it++) {
        cpa_wait0();
        __syncthreads();
        if (it + 1 < NIT) DN_LOAD((it + 1) & 1, (it + 1) * TK);
        unsigned st = (it & 1) * str;

#pragma unroll
        for (int kk = 0; kk < TK; kk += 16) {
            unsigned aH[2][4];
#pragma unroll
            for (int mf = 0; mf < 2; mf++)
                ldsm4(aH[mf][0], aH[mf][1], aH[mf][2], aH[mf][3], sAh + st + aoff[mf] + kk * 2);
#pragma unroll
            for (int nfp = 0; nfp < 4; nfp++) {
                unsigned bB[4];
                ldsm4(bB[0], bB[1], bB[2], bB[3], sBs + st + boff[nfp] + kk * 2);
#pragma unroll
                for (int h2 = 0; h2 < 2; h2++) {
                    int nf = nfp * 2 + h2;
#pragma unroll
                    for (int mf = 0; mf < 2; mf++)
                        mma_f16(acc[mf][nf], aH[mf], &bB[h2 * 2]);
                }
            }
        }
    }
#undef DN_LOAD

    // epilogue: weighted atomic scatter into y (each element gets exactly 2 adds;
    // fp32 add is commutative -> order-independent, deterministic bits).
#pragma unroll
    for (int mf = 0; mf < 2; mf++) {
#pragma unroll
        for (int half = 0; half < 2; half++) {
            int lr = wm * 32 + mf * 16 + g + half * 8;
            int r = m0 + lr;
            if (r < M) {
                int p = prow[lr];
                float w = g_tokw[p];
                float* yr = y + (size_t)(p >> 1) * HDIM;
#pragma unroll
                for (int nf = 0; nf < 8; nf++) {
                    int col = n0 + wn * 64 + nf * 8 + 2 * q;
                    atomicAdd(&yr[col],     w * acc[mf][nf][half * 2 + 0]);
                    atomicAdd(&yr[col + 1], w * acc[mf][nf][half * 2 + 1]);
                }
            }
        }
    }
}

// ---------------- launch: fork-join capture for parallel graph branches ----------------
extern "C" void kernel_launch(void* const* d_in, const int* in_sizes, int n_in,
                              void* d_out, int out_size) {
    const float* x  = (const float*)d_in[0];
    const float* gw = (const float*)d_in[1];
    const float* wg = (const float*)d_in[2];
    const float* wu = (const float*)d_in[3];
    const float* wd = (const float*)d_in[4];
    float* y = (float*)d_out;

    cudaFuncSetAttribute(gateup_kernel, cudaFuncAttributeMaxDynamicSharedMemorySize, GU_SMEM);

    cudaStream_t s2;
    cudaEvent_t evA, evB;
    bool forked =
        (cudaStreamCreateWithFlags(&s2, cudaStreamNonBlocking) == cudaSuccess);
    if (forked && cudaEventCreateWithFlags(&evA, cudaEventDisableTiming) != cudaSuccess)
        forked = false;
    if (forked && cudaEventCreateWithFlags(&evB, cudaEventDisableTiming) != cudaSuccess)
        forked = false;

    if (forked) {
        // fork: side branch does output-zero + weight transposes (BW-bound);
        // main branch does router + aux (latency-bound). Disjoint data.
        cudaEventRecord(evA, 0);
        cudaStreamWaitEvent(s2, evA, 0);
        zero_y_kernel<<<(NTOK * HDIM / 4) / 256, 256, 0, s2>>>(y);
        transpose_half_kernel<0><<<dim3(IDIM / 64, HDIM / 64, EEXP), 256, 0, s2>>>(wg, HDIM, IDIM);
        transpose_half_kernel<1><<<dim3(IDIM / 64, HDIM / 64, EEXP), 256, 0, s2>>>(wu, HDIM, IDIM);
        transpose_half_kernel<2><<<dim3(HDIM / 64, IDIM / 64, EEXP), 256, 0, s2>>>(wd, IDIM, HDIM);
        cudaEventRecord(evB, s2);

        reset_kernel<<<1, 32>>>();
        router_kernel<<<NTOK / 8, 256>>>(x, gw);
        aux_partial_kernel<<<AUXB, 256>>>();
        aux_final_kernel<<<1, 32>>>(y + (out_size - 1));

        // join: gateup needs router + wg/wu; down needs zero_y + wd.
        cudaStreamWaitEvent(0, evB, 0);
        gateup_kernel<<<dim3(IDIM / TN, (NTOK * 2) / TM, EEXP), 256, GU_SMEM>>>();
        down_kernel<<<dim3(HDIM / TN, (NTOK * 2) / TM, EEXP), 256>>>(y);
    } else {
        // serial fallback (identical math)
        reset_kernel<<<1, 32>>>();
        zero_y_kernel<<<(NTOK * HDIM / 4) / 256, 256>>>(y);
        router_kernel<<<NTOK / 8, 256>>>(x, gw);
        aux_partial_kernel<<<AUXB, 256>>>();
        aux_final_kernel<<<1, 32>>>(y + (out_size - 1));
        transpose_half_kernel<0><<<dim3(IDIM / 64, HDIM / 64, EEXP), 256>>>(wg, HDIM, IDIM);
        transpose_half_kernel<1><<<dim3(IDIM / 64, HDIM / 64, EEXP), 256>>>(wu, HDIM, IDIM);
        transpose_half_kernel<2><<<dim3(HDIM / 64, IDIM / 64, EEXP), 256>>>(wd, IDIM, HDIM);
        gateup_kernel<<<dim3(IDIM / TN, (NTOK * 2) / TM, EEXP), 256, GU_SMEM>>>();
        down_kernel<<<dim3(HDIM / TN, (NTOK * 2) / TM, EEXP), 256>>>(y);
    }
}